// round 13
// baseline (speedup 1.0000x reference)
#include <cuda_runtime.h>
#include <cstdint>

#define NMAX   200704      // >= N=200000, bounds all clamped gathers
#define KNBR   64
#define TPB    128
#define PPB    64          // points per block (2 threads/point)
#define SROW   66          // smem row stride (words) per point
#define HOFF   33          // offset of second half within a row

__device__ float4 g_table[NMAX];
__device__ int    g_is32;   // 1 if neighbor_matrix is actually int32 data

// ---------------------------------------------------------------------------
// pack: build (x,y,z,u) float4 table. Block 0 also classifies the neighbor
// buffer dtype (JAX silently demotes int64->int32 without x64): int32 data
// read as int64 yields values outside [-1, n) with overwhelming probability
// over 2048 samples. Deterministic every replay.
// ---------------------------------------------------------------------------
__global__ void pack_kernel(const float* __restrict__ coords,
                            const float* __restrict__ y,
                            const long long* __restrict__ nb,
                            int nb_elems, int n)
{
    int i = blockIdx.x * blockDim.x + threadIdx.x;
    if (i < n) {
        g_table[i] = make_float4(coords[3 * i + 0],
                                 coords[3 * i + 1],
                                 coords[3 * i + 2],
                                 y[i]);
    }
    if (blockIdx.x == 0) {
        int bad = 0;
        int lim = nb_elems / 2;
        if (lim > 2048) lim = 2048;
        for (int t = threadIdx.x; t < lim; t += blockDim.x) {
            long long v = nb[t];
            if (v < -1 || v >= (long long)n) bad = 1;
        }
        bad = __syncthreads_or(bad);
        if (threadIdx.x == 0) g_is32 = bad;
    }
}

// ---------------------------------------------------------------------------
// deriv: TWO THREADS per point (64 points / 128-thread block) — the proven
// r12 structure. NEW: staging stores READY-TO-USE BYTE OFFSETS (index*16,
// with the -1 mask already clamped to the owning point, which staging knows
// as base+pt). The 12.8M-iteration gather loop shrinks from
// LDS->ISETP->SEL->IMAD->LDG to LDS->IMAD.WIDE->LDG: shorter dependency
// chain and ~2 fewer issue slots per neighbor.
// One shfl.bfly(1) combines the 9 partial sums; both lanes then hold full
// sums — even lane solves+stores x,y; odd lane stores z.
// Smem: [64 points][66 words]; thread (p,h) reads words h*33 + m, m=0..31.
// Bank = (2p + h + m) mod 32 -> bijective over a warp => conflict-free.
// ---------------------------------------------------------------------------
__global__ __launch_bounds__(TPB, 8)
void deriv_kernel(const void* __restrict__ nb_raw,
                  float* __restrict__ out, int n)
{
    __shared__ int soff[PPB * SROW];     // byte offsets into g_table

    const int tid  = threadIdx.x;
    const int base = blockIdx.x * PPB;
    const bool is32 = (g_is32 != 0);

    const int p    = tid >> 1;           // local point 0..63
    const int half = tid & 1;            // which 32 neighbors
    const int i    = base + p;           // global point (< NMAX by grid bound)

    // Hoisted: overlap center load latency with index staging.
    const float4 c = g_table[i];

    // ---- stage 64x64 neighbor byte-offsets, coalesced wide loads ----
    if (is32) {
        const int4* __restrict__ nb4 = (const int4*)nb_raw;
        const size_t gbase = (size_t)blockIdx.x * (PPB * KNBR / 4);
        #pragma unroll
        for (int jj = 0; jj < 8; jj++) {
            int l  = tid + jj * TPB;         // 0..1023
            int pt = l >> 4;                 // local point
            int c4 = l & 15;                 // which int4 in the row
            int4 v = make_int4(-1, -1, -1, -1);
            if (base + pt < n) v = nb4[gbase + l];
            int self = base + pt;            // clamp target for masked (-1)
            int o0 = ((v.x < 0) ? self : v.x) << 4;
            int o1 = ((v.y < 0) ? self : v.y) << 4;
            int o2 = ((v.z < 0) ? self : v.z) << 4;
            int o3 = ((v.w < 0) ? self : v.w) << 4;
            int hh = c4 >> 3;                // half
            int mm = (c4 & 7) * 4;           // word within half
            int* r = &soff[pt * SROW + hh * HOFF + mm];
            r[0] = o0; r[1] = o1; r[2] = o2; r[3] = o3;
        }
    } else {
        const longlong2* __restrict__ nb2 = (const longlong2*)nb_raw;
        const size_t gbase = (size_t)blockIdx.x * (PPB * KNBR / 2);
        #pragma unroll
        for (int jj = 0; jj < 16; jj++) {
            int l  = tid + jj * TPB;         // 0..2047
            int pt = l >> 5;
            int c2 = l & 31;
            longlong2 v = make_longlong2(-1, -1);
            if (base + pt < n) v = nb2[gbase + l];
            int self = base + pt;
            int o0 = ((v.x < 0) ? self : (int)v.x) << 4;
            int o1 = ((v.y < 0) ? self : (int)v.y) << 4;
            int hh = c2 >> 4;
            int mm = (c2 & 15) * 2;
            int* r = &soff[pt * SROW + hh * HOFF + mm];
            r[0] = o0; r[1] = o1;
        }
    }
    __syncthreads();

    float axx = 0.f, axy = 0.f, axz = 0.f;
    float ayy = 0.f, ayz = 0.f, azz = 0.f;
    float bx  = 0.f, by  = 0.f, bz  = 0.f;

    const int* __restrict__ row = &soff[p * SROW + half * HOFF];
    const char* __restrict__ tbase = (const char*)g_table;

    #pragma unroll 8
    for (int k = 0; k < 32; k++) {
        int off = row[k];                    // ready byte offset (mask pre-clamped)
        const float4 t = __ldg((const float4*)(tbase + off));

        float dx = t.x - c.x;
        float dy = t.y - c.y;
        float dz = t.z - c.z;
        float du = t.w - c.w;

        float r2 = fmaf(dx, dx, fmaf(dy, dy, fmaf(dz, dz, 1e-8f)));
        float w;
        asm("rcp.approx.f32 %0, %1;" : "=f"(w) : "f"(r2));

        float wdx = w * dx, wdy = w * dy, wdz = w * dz;
        axx = fmaf(wdx, dx, axx);
        axy = fmaf(wdx, dy, axy);
        axz = fmaf(wdx, dz, axz);
        ayy = fmaf(wdy, dy, ayy);
        ayz = fmaf(wdy, dz, ayz);
        azz = fmaf(wdz, dz, azz);
        bx  = fmaf(wdx, du, bx);
        by  = fmaf(wdy, du, by);
        bz  = fmaf(wdz, du, bz);
    }

    // ---- pair reduction: lanes 2a and 2a+1 combine (xor 1) ----
    // After this, BOTH lanes hold the complete sums.
    const unsigned FULL = 0xffffffffu;
    axx += __shfl_xor_sync(FULL, axx, 1);
    axy += __shfl_xor_sync(FULL, axy, 1);
    axz += __shfl_xor_sync(FULL, axz, 1);
    ayy += __shfl_xor_sync(FULL, ayy, 1);
    ayz += __shfl_xor_sync(FULL, ayz, 1);
    azz += __shfl_xor_sync(FULL, azz, 1);
    bx  += __shfl_xor_sync(FULL, bx , 1);
    by  += __shfl_xor_sync(FULL, by , 1);
    bz  += __shfl_xor_sync(FULL, bz , 1);

    if (i < n) {
        // Tikhonov regularizer
        axx += 1e-6f; ayy += 1e-6f; azz += 1e-6f;

        // Symmetric 3x3 solve via adjugate (Cramer) — both lanes compute
        // (identical inputs -> identical results); each stores its share.
        float m00 = fmaf(ayy, azz, -ayz * ayz);
        float m01 = fmaf(axz, ayz, -axy * azz);
        float m02 = fmaf(axy, ayz, -axz * ayy);
        float m11 = fmaf(axx, azz, -axz * axz);
        float m12 = fmaf(axy, axz, -axx * ayz);
        float m22 = fmaf(axx, ayy, -axy * axy);

        float det = fmaf(axx, m00, fmaf(axy, m01, axz * m02));
        float inv;
        asm("rcp.approx.f32 %0, %1;" : "=f"(inv) : "f"(det));

        if (half == 0) {
            float gx = fmaf(m00, bx, fmaf(m01, by, m02 * bz)) * inv;
            float gy = fmaf(m01, bx, fmaf(m11, by, m12 * bz)) * inv;
            out[3 * i + 0] = gx;
            out[3 * i + 1] = gy;
        } else {
            float gz = fmaf(m02, bx, fmaf(m12, by, m22 * bz)) * inv;
            out[3 * i + 2] = gz;
        }
    }
}

// ---------------------------------------------------------------------------
extern "C" void kernel_launch(void* const* d_in, const int* in_sizes, int n_in,
                              void* d_out, int out_size)
{
    const float* coords = (const float*)d_in[0];   // [N, 3] float32
    const void*  nb     = d_in[1];                 // [N, 64] int64 (demoted int32 in practice)
    const float* yv     = (const float*)d_in[2];   // [N, 1] float32
    float*       out    = (float*)d_out;           // [N, 3] float32

    const int n = in_sizes[0] / 3;

    pack_kernel<<<(n + 255) / 256, 256>>>(coords, yv,
                                          (const long long*)nb, in_sizes[1], n);
    deriv_kernel<<<(n + PPB - 1) / PPB, TPB>>>(nb, out, n);
}

// round 14
// speedup vs baseline: 1.0018x; 1.0018x over previous
#include <cuda_runtime.h>
#include <cstdint>

#define NMAX   200704      // >= N=200000, bounds all clamped gathers
#define KNBR   64
#define TPB    128
#define PPB    64          // points per block (2 threads/point)
#define SROW   66          // smem row stride (words) per point
#define HOFF   33          // offset of second half within a row

__device__ float4 g_table[NMAX];
__device__ int    g_is32;   // 1 if neighbor_matrix is actually int32 data

// ---------------------------------------------------------------------------
// pack: build (x,y,z,u) float4 table. Block 0 also classifies the neighbor
// buffer dtype (JAX silently demotes int64->int32 without x64): int32 data
// read as int64 yields values outside [-1, n) with overwhelming probability
// over 2048 samples. Deterministic every replay.
// ---------------------------------------------------------------------------
__global__ void pack_kernel(const float* __restrict__ coords,
                            const float* __restrict__ y,
                            const long long* __restrict__ nb,
                            int nb_elems, int n)
{
    int i = blockIdx.x * blockDim.x + threadIdx.x;
    if (i < n) {
        g_table[i] = make_float4(coords[3 * i + 0],
                                 coords[3 * i + 1],
                                 coords[3 * i + 2],
                                 y[i]);
    }
    if (blockIdx.x == 0) {
        int bad = 0;
        int lim = nb_elems / 2;
        if (lim > 2048) lim = 2048;
        for (int t = threadIdx.x; t < lim; t += blockDim.x) {
            long long v = nb[t];
            if (v < -1 || v >= (long long)n) bad = 1;
        }
        bad = __syncthreads_or(bad);
        if (threadIdx.x == 0) g_is32 = bad;
    }
}

// ---------------------------------------------------------------------------
// deriv: TWO THREADS per point (64 points / 128-thread block) — the proven
// r12/r13 structure (best of 10 measured variants). Staging stores ready
// byte offsets (index*16, -1 pre-clamped to the owning point). Gather loop:
// LDS -> IMAD.WIDE -> LDG, fully unrolled. One shfl.bfly(1) combines the 9
// partial sums; both lanes hold full sums — even lane stores x,y; odd z.
// This round: full blocks (all but the last of 3125) take an UNGUARDED
// staging path (no per-iteration bound predicates).
// Smem: [64 points][66 words]; thread (p,h) reads words h*33 + m, m=0..31.
// Bank = (2p + h + m) mod 32 -> bijective over a warp => conflict-free.
// ---------------------------------------------------------------------------
__global__ __launch_bounds__(TPB, 8)
void deriv_kernel(const void* __restrict__ nb_raw,
                  float* __restrict__ out, int n)
{
    __shared__ int soff[PPB * SROW];     // byte offsets into g_table

    const int tid  = threadIdx.x;
    const int base = blockIdx.x * PPB;
    const bool is32 = (g_is32 != 0);

    const int p    = tid >> 1;           // local point 0..63
    const int half = tid & 1;            // which 32 neighbors
    const int i    = base + p;           // global point (< NMAX by grid bound)

    // Hoisted: overlap center load latency with index staging.
    const float4 c = g_table[i];

    const bool full = (base + PPB <= n);

    // ---- stage 64x64 neighbor byte-offsets, coalesced wide loads ----
    if (is32 && full) {
        // Fast path: no bound predicates.
        const int4* __restrict__ nb4 = (const int4*)nb_raw;
        const size_t gbase = (size_t)blockIdx.x * (PPB * KNBR / 4);
        #pragma unroll
        for (int jj = 0; jj < 8; jj++) {
            int l  = tid + jj * TPB;         // 0..1023
            int pt = l >> 4;                 // local point
            int c4 = l & 15;                 // which int4 in the row
            int4 v = nb4[gbase + l];
            int self = base + pt;            // clamp target for masked (-1)
            int o0 = ((v.x < 0) ? self : v.x) << 4;
            int o1 = ((v.y < 0) ? self : v.y) << 4;
            int o2 = ((v.z < 0) ? self : v.z) << 4;
            int o3 = ((v.w < 0) ? self : v.w) << 4;
            int hh = c4 >> 3;                // half
            int mm = (c4 & 7) * 4;           // word within half
            int* r = &soff[pt * SROW + hh * HOFF + mm];
            r[0] = o0; r[1] = o1; r[2] = o2; r[3] = o3;
        }
    } else if (is32) {
        const int4* __restrict__ nb4 = (const int4*)nb_raw;
        const size_t gbase = (size_t)blockIdx.x * (PPB * KNBR / 4);
        #pragma unroll
        for (int jj = 0; jj < 8; jj++) {
            int l  = tid + jj * TPB;
            int pt = l >> 4;
            int c4 = l & 15;
            int4 v = make_int4(-1, -1, -1, -1);
            if (base + pt < n) v = nb4[gbase + l];
            int self = base + pt;
            int o0 = ((v.x < 0) ? self : v.x) << 4;
            int o1 = ((v.y < 0) ? self : v.y) << 4;
            int o2 = ((v.z < 0) ? self : v.z) << 4;
            int o3 = ((v.w < 0) ? self : v.w) << 4;
            int hh = c4 >> 3;
            int mm = (c4 & 7) * 4;
            int* r = &soff[pt * SROW + hh * HOFF + mm];
            r[0] = o0; r[1] = o1; r[2] = o2; r[3] = o3;
        }
    } else {
        const longlong2* __restrict__ nb2 = (const longlong2*)nb_raw;
        const size_t gbase = (size_t)blockIdx.x * (PPB * KNBR / 2);
        #pragma unroll
        for (int jj = 0; jj < 16; jj++) {
            int l  = tid + jj * TPB;         // 0..2047
            int pt = l >> 5;
            int c2 = l & 31;
            longlong2 v = make_longlong2(-1, -1);
            if (base + pt < n) v = nb2[gbase + l];
            int self = base + pt;
            int o0 = ((v.x < 0) ? self : (int)v.x) << 4;
            int o1 = ((v.y < 0) ? self : (int)v.y) << 4;
            int hh = c2 >> 4;
            int mm = (c2 & 15) * 2;
            int* r = &soff[pt * SROW + hh * HOFF + mm];
            r[0] = o0; r[1] = o1;
        }
    }
    __syncthreads();

    float axx = 0.f, axy = 0.f, axz = 0.f;
    float ayy = 0.f, ayz = 0.f, azz = 0.f;
    float bx  = 0.f, by  = 0.f, bz  = 0.f;

    const int* __restrict__ row = &soff[p * SROW + half * HOFF];
    const char* __restrict__ tbase = (const char*)g_table;

    #pragma unroll
    for (int k = 0; k < 32; k++) {
        int off = row[k];                    // ready byte offset (mask pre-clamped)
        const float4 t = __ldg((const float4*)(tbase + off));

        float dx = t.x - c.x;
        float dy = t.y - c.y;
        float dz = t.z - c.z;
        float du = t.w - c.w;

        float r2 = fmaf(dx, dx, fmaf(dy, dy, fmaf(dz, dz, 1e-8f)));
        float w;
        asm("rcp.approx.f32 %0, %1;" : "=f"(w) : "f"(r2));

        float wdx = w * dx, wdy = w * dy, wdz = w * dz;
        axx = fmaf(wdx, dx, axx);
        axy = fmaf(wdx, dy, axy);
        axz = fmaf(wdx, dz, axz);
        ayy = fmaf(wdy, dy, ayy);
        ayz = fmaf(wdy, dz, ayz);
        azz = fmaf(wdz, dz, azz);
        bx  = fmaf(wdx, du, bx);
        by  = fmaf(wdy, du, by);
        bz  = fmaf(wdz, du, bz);
    }

    // ---- pair reduction: lanes 2a and 2a+1 combine (xor 1) ----
    // After this, BOTH lanes hold the complete sums.
    const unsigned FULL = 0xffffffffu;
    axx += __shfl_xor_sync(FULL, axx, 1);
    axy += __shfl_xor_sync(FULL, axy, 1);
    axz += __shfl_xor_sync(FULL, axz, 1);
    ayy += __shfl_xor_sync(FULL, ayy, 1);
    ayz += __shfl_xor_sync(FULL, ayz, 1);
    azz += __shfl_xor_sync(FULL, azz, 1);
    bx  += __shfl_xor_sync(FULL, bx , 1);
    by  += __shfl_xor_sync(FULL, by , 1);
    bz  += __shfl_xor_sync(FULL, bz , 1);

    if (i < n) {
        // Tikhonov regularizer
        axx += 1e-6f; ayy += 1e-6f; azz += 1e-6f;

        // Symmetric 3x3 solve via adjugate (Cramer) — both lanes compute
        // (identical inputs -> identical results); each stores its share.
        float m00 = fmaf(ayy, azz, -ayz * ayz);
        float m01 = fmaf(axz, ayz, -axy * azz);
        float m02 = fmaf(axy, ayz, -axz * ayy);
        float m11 = fmaf(axx, azz, -axz * axz);
        float m12 = fmaf(axy, axz, -axx * ayz);
        float m22 = fmaf(axx, ayy, -axy * axy);

        float det = fmaf(axx, m00, fmaf(axy, m01, axz * m02));
        float inv;
        asm("rcp.approx.f32 %0, %1;" : "=f"(inv) : "f"(det));

        if (half == 0) {
            float gx = fmaf(m00, bx, fmaf(m01, by, m02 * bz)) * inv;
            float gy = fmaf(m01, bx, fmaf(m11, by, m12 * bz)) * inv;
            out[3 * i + 0] = gx;
            out[3 * i + 1] = gy;
        } else {
            float gz = fmaf(m02, bx, fmaf(m12, by, m22 * bz)) * inv;
            out[3 * i + 2] = gz;
        }
    }
}

// ---------------------------------------------------------------------------
extern "C" void kernel_launch(void* const* d_in, const int* in_sizes, int n_in,
                              void* d_out, int out_size)
{
    const float* coords = (const float*)d_in[0];   // [N, 3] float32
    const void*  nb     = d_in[1];                 // [N, 64] int64 (demoted int32 in practice)
    const float* yv     = (const float*)d_in[2];   // [N, 1] float32
    float*       out    = (float*)d_out;           // [N, 3] float32

    const int n = in_sizes[0] / 3;

    pack_kernel<<<(n + 255) / 256, 256>>>(coords, yv,
                                          (const long long*)nb, in_sizes[1], n);
    deriv_kernel<<<(n + PPB - 1) / PPB, TPB>>>(nb, out, n);
}